// round 4
// baseline (speedup 1.0000x reference)
#include <cuda_runtime.h>
#include <cuda_bf16.h>

// ---------------- problem constants ----------------
#define T_STEPS 192
#define B_SZ    128
#define IN_SZ   512
#define R_SZ    1024
#define OUT_SZ  100
#define PS      64
#define BR      (B_SZ * R_SZ)          // 131072
#define SPK_ELEMS (T_STEPS * BR)       // 25165824
#define OUT_ELEMS (B_SZ * OUT_SZ)      // 12800
#define ALPHA 0.9f
#define BETA  0.9f

#define NBLK 128          // persistent grid
#define MSLAB 64          // b-rows per CTA
#define NTILE 16          // r-cols per CTA
#define KTOT 2048         // combined K (W_rec ++ W_lin)
#define CHUNK 64          // k-chunk staged per iteration
#define SB_STRIDE 68      // padded smem row stride for spike buffer

// ---------------- device scratch ----------------
__device__ float g_cur[T_STEPS * BR];              // input projection (+b_in)
__device__ __nv_bfloat16 g_spkb[T_STEPS * BR];     // spike history, bf16 (exact 0/1)
__device__ float g_ro[B_SZ * 3 * R_SZ];            // readout input
__device__ unsigned g_bar_count;
__device__ unsigned g_bar_phase;

typedef unsigned long long ull;

__device__ __forceinline__ ull pack2(float lo, float hi) {
    ull r; asm("mov.b64 %0, {%1,%2};" : "=l"(r) : "f"(lo), "f"(hi)); return r;
}
__device__ __forceinline__ void fma2(ull &d, ull a, ull b) {
    asm("fma.rn.f32x2 %0, %1, %2, %0;" : "+l"(d) : "l"(a), "l"(b));
}
__device__ __forceinline__ float2 unpack2(ull v) {
    float2 r; asm("mov.b64 {%0,%1}, %2;" : "=f"(r.x), "=f"(r.y) : "l"(v)); return r;
}

// ---------------- init barrier state ----------------
__global__ void k_init() {
    if (threadIdx.x == 0 && blockIdx.x == 0) {
        g_bar_count = 0;
        g_bar_phase = 0;
    }
}

// ---------------- grid barrier (all NBLK CTAs resident) ----------------
__device__ __forceinline__ void grid_bar(unsigned target) {
    __syncthreads();
    if (threadIdx.x == 0) {
        __threadfence();
        unsigned t = atomicAdd(&g_bar_count, 1u);
        if (t == NBLK - 1) {
            g_bar_count = 0;
            __threadfence();
            atomicExch(&g_bar_phase, target);
        } else {
            while (atomicAdd(&g_bar_phase, 0u) < target) { __nanosleep(64); }
        }
        __threadfence();
    }
    __syncthreads();
}

// ---------------- input projection GEMM (unchanged from R1) ----------------
__global__ void k_input_gemm(const float* __restrict__ X,
                             const float* __restrict__ Win,
                             const float* __restrict__ bin) {
    __shared__ float As[16][128];
    __shared__ float Bs[16][128];
    int tid = threadIdx.x;
    int n0 = blockIdx.x * 128;
    int m0 = blockIdx.y * 128;
    int p  = m0 >> 13;
    const float* A = X + (size_t)m0 * IN_SZ;
    const float* W = Win + (size_t)p * R_SZ * IN_SZ + (size_t)n0 * IN_SZ;

    int lr = tid >> 2;
    int lk = (tid & 3) * 4;
    int tx = tid & 15, ty = tid >> 4;

    ull acc[8][4];
#pragma unroll
    for (int i = 0; i < 8; i++)
#pragma unroll
        for (int j = 0; j < 4; j++) acc[i][j] = 0ULL;

    for (int k0 = 0; k0 < IN_SZ; k0 += 16) {
        float4 a0 = *(const float4*)(A + (size_t)lr * IN_SZ + k0 + lk);
        float4 a1 = *(const float4*)(A + (size_t)(lr + 64) * IN_SZ + k0 + lk);
        float4 b0 = *(const float4*)(W + (size_t)lr * IN_SZ + k0 + lk);
        float4 b1 = *(const float4*)(W + (size_t)(lr + 64) * IN_SZ + k0 + lk);
        __syncthreads();
        As[lk + 0][lr] = a0.x; As[lk + 1][lr] = a0.y; As[lk + 2][lr] = a0.z; As[lk + 3][lr] = a0.w;
        As[lk + 0][lr + 64] = a1.x; As[lk + 1][lr + 64] = a1.y; As[lk + 2][lr + 64] = a1.z; As[lk + 3][lr + 64] = a1.w;
        Bs[lk + 0][lr] = b0.x; Bs[lk + 1][lr] = b0.y; Bs[lk + 2][lr] = b0.z; Bs[lk + 3][lr] = b0.w;
        Bs[lk + 0][lr + 64] = b1.x; Bs[lk + 1][lr + 64] = b1.y; Bs[lk + 2][lr + 64] = b1.z; Bs[lk + 3][lr + 64] = b1.w;
        __syncthreads();
#pragma unroll
        for (int kk = 0; kk < 16; kk++) {
            float4 af0 = *(float4*)&As[kk][ty * 8];
            float4 af1 = *(float4*)&As[kk][ty * 8 + 4];
            float4 bf0 = *(float4*)&Bs[kk][tx * 8];
            float4 bf1 = *(float4*)&Bs[kk][tx * 8 + 4];
            ull b2[4] = { pack2(bf0.x, bf0.y), pack2(bf0.z, bf0.w),
                          pack2(bf1.x, bf1.y), pack2(bf1.z, bf1.w) };
            float am[8] = { af0.x, af0.y, af0.z, af0.w, af1.x, af1.y, af1.z, af1.w };
#pragma unroll
            for (int i = 0; i < 8; i++) {
                ull a2 = pack2(am[i], am[i]);
#pragma unroll
                for (int j = 0; j < 4; j++) fma2(acc[i][j], a2, b2[j]);
            }
        }
    }
    float* C = g_cur + (size_t)m0 * R_SZ + n0;
#pragma unroll
    for (int i = 0; i < 8; i++) {
        int m = ty * 8 + i;
#pragma unroll
        for (int j = 0; j < 4; j++) {
            float2 v = unpack2(acc[i][j]);
            int n = tx * 8 + j * 2;
            C[(size_t)m * R_SZ + n]     = v.x + __ldg(bin + n0 + n);
            C[(size_t)m * R_SZ + n + 1] = v.y + __ldg(bin + n0 + n + 1);
        }
    }
}

// ---------------- persistent scan kernel ----------------
// Grid: 128 CTAs. CTA bid: mi = bid>>6 (b-slab of 64), ni = bid&63 (r-tile of 16).
// smem: Ws[2048][16] fp32 weights (resident), sbuf[2][64][SB_STRIDE] spike staging.
// Thread (tx = tid&3, ty = tid>>2): outputs b = m0+ty, r = n0 + tx*4 .. +3.
__global__ void __launch_bounds__(256, 1)
k_scan(const float* __restrict__ Wrec,
       const float* __restrict__ Wlin,
       const float* __restrict__ brec,
       float* __restrict__ spk_out) {
    extern __shared__ float smem[];
    float* Ws  = smem;                       // [KTOT][NTILE]
    float* sb0 = smem + KTOT * NTILE;        // [MSLAB][SB_STRIDE]
    float* sb1 = sb0 + MSLAB * SB_STRIDE;

    const int tid = threadIdx.x;
    const int bid = blockIdx.x;
    const int mi = bid >> 6;                 // 0..1
    const int ni = bid & 63;                 // 0..63
    const int m0 = mi * MSLAB;
    const int n0 = ni * NTILE;

    const int tx = tid & 3;                  // n-group
    const int ty = tid >> 2;                 // m row (0..63)

    // ---- load resident weight slab: Ws[k][n] ----
    {
        int n = tid & 15;
        int kq = tid >> 4;                   // 0..15
        const float* wr = Wrec + (size_t)(n0 + n) * R_SZ;
        const float* wl = Wlin + (size_t)(n0 + n) * R_SZ;
        for (int j = 0; j < 16; j++) {
            int kf = kq + j * 16;            // float4 index 0..255
            float4 v = *(const float4*)(wr + kf * 4);
            int k = kf * 4;
            Ws[(k + 0) * NTILE + n] = v.x;
            Ws[(k + 1) * NTILE + n] = v.y;
            Ws[(k + 2) * NTILE + n] = v.z;
            Ws[(k + 3) * NTILE + n] = v.w;
        }
        for (int j = 0; j < 16; j++) {
            int kf = kq + j * 16;
            float4 v = *(const float4*)(wl + kf * 4);
            int k = 1024 + kf * 4;
            Ws[(k + 0) * NTILE + n] = v.x;
            Ws[(k + 1) * NTILE + n] = v.y;
            Ws[(k + 2) * NTILE + n] = v.z;
            Ws[(k + 3) * NTILE + n] = v.w;
        }
    }
    __syncthreads();

    // ---- persistent state ----
    float4 syn = make_float4(0.f, 0.f, 0.f, 0.f);
    float4 mem = make_float4(0.f, 0.f, 0.f, 0.f);
    const float4 br = *(const float4*)(brec + n0 + tx * 4);

    // staging-load indices: 4 threads per row, 16 bf16 each
    const int srow = tid >> 2;               // 0..63
    const int scol = (tid & 3) * 16;

    float* const myrow_out[2] = { sb0 + srow * SB_STRIDE + scol,
                                  sb1 + srow * SB_STRIDE + scol };
    float* const myA0 = sb0 + ty * SB_STRIDE;
    float* const myA1 = sb1 + ty * SB_STRIDE;

    for (int t = 0; t < T_STEPS; t++) {
        float4 cur = *(const float4*)(g_cur + (size_t)t * BR + (size_t)(m0 + ty) * R_SZ + n0 + tx * 4);

        ull acc0 = 0ULL, acc1 = 0ULL;

        // combined pass list: (source time, Ws k-base), up to 2
        int nsrc = (t == 0) ? 0 : ((t > PS) ? 2 : 1);

        for (int s = 0; s < nsrc; s++) {
            const int tsrc = (s == 0) ? (t - 1) : (t - PS);
            const int kbase = (s == 0) ? 0 : 1024;
            const __nv_bfloat16* src =
                g_spkb + (size_t)tsrc * BR + (size_t)(m0 + srow) * R_SZ + scol;

            // prefetch chunk 0
            uint4 p0 = *(const uint4*)(src);
            uint4 p1 = *(const uint4*)(src + 8);

            const int NCH = 1024 / CHUNK;    // 16
            for (int c = 0; c < NCH; c++) {
                // store current regs into buffer c&1
                float* dst = myrow_out[c & 1];
                {
                    const __nv_bfloat162* h0 = (const __nv_bfloat162*)&p0;
                    const __nv_bfloat162* h1 = (const __nv_bfloat162*)&p1;
#pragma unroll
                    for (int i = 0; i < 4; i++) {
                        float2 f = __bfloat1622float2(h0[i]);
                        dst[i * 2]     = f.x;
                        dst[i * 2 + 1] = f.y;
                    }
#pragma unroll
                    for (int i = 0; i < 4; i++) {
                        float2 f = __bfloat1622float2(h1[i]);
                        dst[8 + i * 2]     = f.x;
                        dst[8 + i * 2 + 1] = f.y;
                    }
                }
                __syncthreads();
                // prefetch next chunk
                if (c + 1 < NCH) {
                    const __nv_bfloat16* nsrc_p = src + (c + 1) * CHUNK;
                    p0 = *(const uint4*)(nsrc_p);
                    p1 = *(const uint4*)(nsrc_p + 8);
                }
                // compute on buffer c&1
                const float* A = (c & 1) ? myA1 : myA0;
                const float* Wp = Ws + (kbase + c * CHUNK) * NTILE + tx * 4;
#pragma unroll 8
                for (int kk = 0; kk < CHUNK; kk++) {
                    float a = A[kk];
                    float4 w = *(const float4*)(Wp + kk * NTILE);
                    ull a2 = pack2(a, a);
                    fma2(acc0, a2, pack2(w.x, w.y));
                    fma2(acc1, a2, pack2(w.z, w.w));
                }
                __syncthreads();
            }
        }

        float2 s01 = unpack2(acc0);
        float2 s23 = unpack2(acc1);

        float4 spk;
        {
            syn.x = ALPHA * syn.x + cur.x + s01.x + br.x;
            float rs = (mem.x > 1.0f) ? 1.0f : 0.0f;
            mem.x = BETA * mem.x + syn.x - rs;
            spk.x = (mem.x > 1.0f) ? 1.0f : 0.0f;

            syn.y = ALPHA * syn.y + cur.y + s01.y + br.y;
            rs = (mem.y > 1.0f) ? 1.0f : 0.0f;
            mem.y = BETA * mem.y + syn.y - rs;
            spk.y = (mem.y > 1.0f) ? 1.0f : 0.0f;

            syn.z = ALPHA * syn.z + cur.z + s23.x + br.z;
            rs = (mem.z > 1.0f) ? 1.0f : 0.0f;
            mem.z = BETA * mem.z + syn.z - rs;
            spk.z = (mem.z > 1.0f) ? 1.0f : 0.0f;

            syn.w = ALPHA * syn.w + cur.w + s23.y + br.w;
            rs = (mem.w > 1.0f) ? 1.0f : 0.0f;
            mem.w = BETA * mem.w + syn.w - rs;
            spk.w = (mem.w > 1.0f) ? 1.0f : 0.0f;
        }

        // write spikes: bf16 history + fp32 external
        size_t ofs = (size_t)t * BR + (size_t)(m0 + ty) * R_SZ + n0 + tx * 4;
        {
            __nv_bfloat162 h0 = __floats2bfloat162_rn(spk.x, spk.y);
            __nv_bfloat162 h1 = __floats2bfloat162_rn(spk.z, spk.w);
            uint2 v;
            v.x = *(unsigned*)&h0;
            v.y = *(unsigned*)&h1;
            *(uint2*)(g_spkb + ofs) = v;
        }
        if (spk_out) *(float4*)(spk_out + ofs) = spk;

        grid_bar((unsigned)(t + 1));
    }
}

// ---------------- readout mean over each partition ----------------
__global__ void k_ro_reduce() {
    int e = (blockIdx.x * 256 + threadIdx.x) * 4;   // over B*3R = 393216
    int b = e / (3 * R_SZ);
    int c = e % (3 * R_SZ);
    int p = c >> 10;
    int r = c & (R_SZ - 1);
    const __nv_bfloat16* base = g_spkb + ((size_t)(p * PS) * B_SZ + b) * R_SZ + r;
    float4 s = make_float4(0.f, 0.f, 0.f, 0.f);
#pragma unroll 8
    for (int st = 0; st < PS; st++) {
        uint2 v = *(const uint2*)(base + (size_t)st * BR);
        float2 f0 = __bfloat1622float2(*(const __nv_bfloat162*)&v.x);
        float2 f1 = __bfloat1622float2(*(const __nv_bfloat162*)&v.y);
        s.x += f0.x; s.y += f0.y; s.z += f1.x; s.w += f1.y;
    }
    float inv = 1.0f / (float)PS;
    s.x *= inv; s.y *= inv; s.z *= inv; s.w *= inv;
    *(float4*)(g_ro + e) = s;
}

// ---------------- final readout GEMM + softmax ----------------
__global__ void k_readout(float* __restrict__ out,
                          const float* __restrict__ Wro,
                          const float* __restrict__ bro) {
    int b = blockIdx.x;
    __shared__ float ro_s[3 * R_SZ];
    __shared__ float logit[112];
    __shared__ float red_sum;
    int tid = threadIdx.x;  // 128 threads

    for (int i = tid * 4; i < 3 * R_SZ; i += 512)
        *(float4*)&ro_s[i] = *(const float4*)(g_ro + (size_t)b * 3 * R_SZ + i);
    __syncthreads();

    int warp = tid >> 5, lane = tid & 31;
    for (int o = warp; o < OUT_SZ; o += 4) {
        const float* w = Wro + (size_t)o * (3 * R_SZ);
        float p0 = 0.f;
        for (int k = lane; k < 3 * R_SZ; k += 32) p0 += ro_s[k] * __ldg(w + k);
#pragma unroll
        for (int off = 16; off; off >>= 1) p0 += __shfl_xor_sync(0xffffffffu, p0, off);
        if (lane == 0) logit[o] = p0 + __ldg(bro + o);
    }
    __syncthreads();
    if (warp == 0) {
        float m = -1e30f;
        for (int i = lane; i < OUT_SZ; i += 32) m = fmaxf(m, logit[i]);
#pragma unroll
        for (int off = 16; off; off >>= 1) m = fmaxf(m, __shfl_xor_sync(0xffffffffu, m, off));
        float sm = 0.f;
        for (int i = lane; i < OUT_SZ; i += 32) {
            float e = expf(logit[i] - m);
            logit[i] = e;
            sm += e;
        }
#pragma unroll
        for (int off = 16; off; off >>= 1) sm += __shfl_xor_sync(0xffffffffu, sm, off);
        if (lane == 0) red_sum = sm;
    }
    __syncthreads();
    float inv = 1.0f / red_sum;
    for (int i = tid; i < OUT_SZ; i += 128)
        out[(size_t)b * OUT_SZ + i] = logit[i] * inv;
}

// ---------------- launcher ----------------
extern "C" void kernel_launch(void* const* d_in, const int* in_sizes, int n_in,
                              void* d_out, int out_size) {
    const float* x     = (const float*)d_in[0];
    const float* W_in  = (const float*)d_in[1];
    const float* b_in  = (const float*)d_in[2];
    const float* W_lin = (const float*)d_in[3];
    const float* W_rec = (const float*)d_in[4];
    const float* b_rec = (const float*)d_in[5];
    const float* W_ro  = (const float*)d_in[6];
    const float* b_ro  = (const float*)d_in[7];

    float* out_main = (float*)d_out;
    float* spk_out  = nullptr;
    if (out_size >= OUT_ELEMS + SPK_ELEMS) {
        spk_out = (float*)d_out + OUT_ELEMS;
    } else if (out_size == SPK_ELEMS) {
        spk_out = (float*)d_out;
        out_main = nullptr;
    }

    static int smem_set = 0;
    const int SMEM_BYTES = (KTOT * NTILE + 2 * MSLAB * SB_STRIDE) * 4;  // 165888
    if (!smem_set) {
        cudaFuncSetAttribute(k_scan, cudaFuncAttributeMaxDynamicSharedMemorySize, SMEM_BYTES);
        smem_set = 1;
    }

    k_init<<<1, 32>>>();
    k_input_gemm<<<dim3(R_SZ / 128, (T_STEPS * B_SZ) / 128), 256>>>(x, W_in, b_in);
    k_scan<<<NBLK, 256, SMEM_BYTES>>>(W_rec, W_lin, b_rec, spk_out);
    k_ro_reduce<<<384, 256>>>();
    if (out_main) k_readout<<<B_SZ, 128>>>(out_main, W_ro, b_ro);
}

// round 6
// speedup vs baseline: 1.8564x; 1.8564x over previous
#include <cuda_runtime.h>

// ---------------- problem constants ----------------
#define T_STEPS 192
#define B_SZ    128
#define IN_SZ   512
#define R_SZ    1024
#define OUT_SZ  100
#define PS      64
#define BR      (B_SZ * R_SZ)          // 131072
#define SPK_ELEMS (T_STEPS * BR)       // 25165824
#define OUT_ELEMS (B_SZ * OUT_SZ)      // 12800
#define ALPHA 0.9f
#define BETA  0.9f

#define GK 256                 // K per split chunk (matches R1 association)
#define NSPLIT_MAX 8
#define ASTRIDE 132            // As[kk][m] row stride (floats)
#define WSTRIDE 68             // Ws[kk][n] row stride (floats)

// ---------------- device scratch ----------------
__device__ float g_cur[T_STEPS * BR];    // input projection (+b_in)
__device__ float g_spk[T_STEPS * BR];    // spike history fp32
__device__ float g_syn[BR];
__device__ float g_mem[BR];
__device__ float g_part[NSPLIT_MAX * BR];// split-K partials
__device__ float g_ro[B_SZ * 3 * R_SZ];  // readout input

typedef unsigned long long ull;

__device__ __forceinline__ ull pack2(float lo, float hi) {
    ull r; asm("mov.b64 %0, {%1,%2};" : "=l"(r) : "f"(lo), "f"(hi)); return r;
}
__device__ __forceinline__ void fma2(ull &d, ull a, ull b) {
    asm("fma.rn.f32x2 %0, %1, %2, %0;" : "+l"(d) : "l"(a), "l"(b));
}
__device__ __forceinline__ float2 unpack2(ull v) {
    float2 r; asm("mov.b64 {%0,%1}, %2;" : "=f"(r.x), "=f"(r.y) : "l"(v)); return r;
}

// ---------------- init: zero syn/mem ----------------
__global__ void k_init() {
    int i = blockIdx.x * blockDim.x + threadIdx.x;
    float4 z = make_float4(0.f, 0.f, 0.f, 0.f);
    *(float4*)(g_syn + i * 4) = z;
    *(float4*)(g_mem + i * 4) = z;
}

// ---------------- input projection GEMM (R1, known-correct) ----------------
__global__ void k_input_gemm(const float* __restrict__ X,
                             const float* __restrict__ Win,
                             const float* __restrict__ bin) {
    __shared__ float As[16][128];
    __shared__ float Bs[16][128];
    int tid = threadIdx.x;
    int n0 = blockIdx.x * 128;
    int m0 = blockIdx.y * 128;
    int p  = m0 >> 13;
    const float* A = X + (size_t)m0 * IN_SZ;
    const float* W = Win + (size_t)p * R_SZ * IN_SZ + (size_t)n0 * IN_SZ;

    int lr = tid >> 2;
    int lk = (tid & 3) * 4;
    int tx = tid & 15, ty = tid >> 4;

    ull acc[8][4];
#pragma unroll
    for (int i = 0; i < 8; i++)
#pragma unroll
        for (int j = 0; j < 4; j++) acc[i][j] = 0ULL;

    for (int k0 = 0; k0 < IN_SZ; k0 += 16) {
        float4 a0 = *(const float4*)(A + (size_t)lr * IN_SZ + k0 + lk);
        float4 a1 = *(const float4*)(A + (size_t)(lr + 64) * IN_SZ + k0 + lk);
        float4 b0 = *(const float4*)(W + (size_t)lr * IN_SZ + k0 + lk);
        float4 b1 = *(const float4*)(W + (size_t)(lr + 64) * IN_SZ + k0 + lk);
        __syncthreads();
        As[lk + 0][lr] = a0.x; As[lk + 1][lr] = a0.y; As[lk + 2][lr] = a0.z; As[lk + 3][lr] = a0.w;
        As[lk + 0][lr + 64] = a1.x; As[lk + 1][lr + 64] = a1.y; As[lk + 2][lr + 64] = a1.z; As[lk + 3][lr + 64] = a1.w;
        Bs[lk + 0][lr] = b0.x; Bs[lk + 1][lr] = b0.y; Bs[lk + 2][lr] = b0.z; Bs[lk + 3][lr] = b0.w;
        Bs[lk + 0][lr + 64] = b1.x; Bs[lk + 1][lr + 64] = b1.y; Bs[lk + 2][lr + 64] = b1.z; Bs[lk + 3][lr + 64] = b1.w;
        __syncthreads();
#pragma unroll
        for (int kk = 0; kk < 16; kk++) {
            float4 af0 = *(float4*)&As[kk][ty * 8];
            float4 af1 = *(float4*)&As[kk][ty * 8 + 4];
            float4 bf0 = *(float4*)&Bs[kk][tx * 8];
            float4 bf1 = *(float4*)&Bs[kk][tx * 8 + 4];
            ull b2[4] = { pack2(bf0.x, bf0.y), pack2(bf0.z, bf0.w),
                          pack2(bf1.x, bf1.y), pack2(bf1.z, bf1.w) };
            float am[8] = { af0.x, af0.y, af0.z, af0.w, af1.x, af1.y, af1.z, af1.w };
#pragma unroll
            for (int i = 0; i < 8; i++) {
                ull a2 = pack2(am[i], am[i]);
#pragma unroll
                for (int j = 0; j < 4; j++) fma2(acc[i][j], a2, b2[j]);
            }
        }
    }
    float* C = g_cur + (size_t)m0 * R_SZ + n0;
#pragma unroll
    for (int i = 0; i < 8; i++) {
        int m = ty * 8 + i;
#pragma unroll
        for (int j = 0; j < 4; j++) {
            float2 v = unpack2(acc[i][j]);
            int n = tx * 8 + j * 2;
            C[(size_t)m * R_SZ + n]     = v.x + __ldg(bin + n0 + n);
            C[(size_t)m * R_SZ + n + 1] = v.y + __ldg(bin + n0 + n + 1);
        }
    }
}

// ---------------- per-step recurrent GEMM v3 ----------------
// grid (16 n-tiles, nsplit), 256 threads. CTA: 128m x 64n, K = 256 chunk.
// ks<4: spk(t-1)@Wrec^T chunk ks*256 ; ks>=4: spk(t-PS)@Wlin^T chunk (ks-4)*256.
// smem: As[32][ASTRIDE] (k-major), Ws[32][WSTRIDE] (k-major), single-buffered,
// register-prefetched in 8 stages of 32 k (R1's proven pattern).
// Thread (tx=tid&15, ty=tid>>4): m = ty*8+{0..7}, n = tx*4+{0..3}.
// Per-output accumulation: one fma per k, k ascending 0..255 (== R1 arithmetic).
__global__ void __launch_bounds__(256)
k_step_gemm(int t,
            const float* __restrict__ Wrec,
            const float* __restrict__ Wlin) {
    const int ks = blockIdx.y;
    const int nt = blockIdx.x;
    const int tid = threadIdx.x;

    const int tsrc = (ks < 4) ? (t - 1) : (t - PS);
    const int kofs = (ks & 3) * GK;
    const float* Asrc = g_spk + (size_t)tsrc * BR + kofs;                  // [128m][1024]
    const float* Wsrc = ((ks < 4) ? Wrec : Wlin) + (size_t)(nt * 64) * R_SZ + kofs;

    __shared__ float As[32 * ASTRIDE];
    __shared__ float Ws[32 * WSTRIDE];

    // A-load mapping: m = tid>>1 (0..127), kq = (tid&1)*4 + j, j 0..3 (float4 idx in 32k)
    const int am = tid >> 1;
    const int akq = (tid & 1) * 4;
    // W-load mapping: n = tid>>2 (0..63), kq2 = (tid&3)*2 + j, j 0..1
    const int wn = tid >> 2;
    const int wkq = (tid & 3) * 2;

    const int tx = tid & 15, ty = tid >> 4;

    ull acc[8][2];
#pragma unroll
    for (int i = 0; i < 8; i++) { acc[i][0] = 0ULL; acc[i][1] = 0ULL; }

    // prefetch stage 0
    float4 ar[4], wr[2];
#pragma unroll
    for (int j = 0; j < 4; j++)
        ar[j] = *(const float4*)(Asrc + (size_t)am * R_SZ + (akq + j) * 4);
#pragma unroll
    for (int j = 0; j < 2; j++)
        wr[j] = *(const float4*)(Wsrc + (size_t)wn * R_SZ + (wkq + j) * 4);

#pragma unroll
    for (int s = 0; s < 8; s++) {
        __syncthreads();
        // store prefetched regs to smem (k-major, transposed)
#pragma unroll
        for (int j = 0; j < 4; j++) {
            int kk = (akq + j) * 4;
            As[(kk + 0) * ASTRIDE + am] = ar[j].x;
            As[(kk + 1) * ASTRIDE + am] = ar[j].y;
            As[(kk + 2) * ASTRIDE + am] = ar[j].z;
            As[(kk + 3) * ASTRIDE + am] = ar[j].w;
        }
#pragma unroll
        for (int j = 0; j < 2; j++) {
            int kk = (wkq + j) * 4;
            Ws[(kk + 0) * WSTRIDE + wn] = wr[j].x;
            Ws[(kk + 1) * WSTRIDE + wn] = wr[j].y;
            Ws[(kk + 2) * WSTRIDE + wn] = wr[j].z;
            Ws[(kk + 3) * WSTRIDE + wn] = wr[j].w;
        }
        __syncthreads();
        // prefetch next stage
        if (s + 1 < 8) {
            const float* An = Asrc + (size_t)am * R_SZ + (s + 1) * 32;
            const float* Wn = Wsrc + (size_t)wn * R_SZ + (s + 1) * 32;
#pragma unroll
            for (int j = 0; j < 4; j++) ar[j] = *(const float4*)(An + (akq + j) * 4);
#pragma unroll
            for (int j = 0; j < 2; j++) wr[j] = *(const float4*)(Wn + (wkq + j) * 4);
        }
        // compute stage s: kk 0..31 (global k ascending)
#pragma unroll 8
        for (int kk = 0; kk < 32; kk++) {
            float4 a0 = *(float4*)&As[kk * ASTRIDE + ty * 8];
            float4 a1 = *(float4*)&As[kk * ASTRIDE + ty * 8 + 4];
            float4 w  = *(float4*)&Ws[kk * WSTRIDE + tx * 4];
            ull wb0 = pack2(w.x, w.y);
            ull wb1 = pack2(w.z, w.w);
            float am8[8] = { a0.x, a0.y, a0.z, a0.w, a1.x, a1.y, a1.z, a1.w };
#pragma unroll
            for (int i = 0; i < 8; i++) {
                ull a2 = pack2(am8[i], am8[i]);
                fma2(acc[i][0], a2, wb0);
                fma2(acc[i][1], a2, wb1);
            }
        }
    }

    // epilogue: partial tile
    float* C = g_part + (size_t)ks * BR + nt * 64;
#pragma unroll
    for (int i = 0; i < 8; i++) {
        int m = ty * 8 + i;
        float2 v01 = unpack2(acc[i][0]);
        float2 v23 = unpack2(acc[i][1]);
        float4 v = make_float4(v01.x, v01.y, v23.x, v23.y);
        *(float4*)(C + (size_t)m * R_SZ + tx * 4) = v;
    }
}

// ---------------- per-step state update (R1 arithmetic, nsplit-aware) ----------------
__global__ void k_update(int t, int nsplit, float* __restrict__ spk_out,
                         const float* __restrict__ brec) {
    int idx = (blockIdx.x * 256 + threadIdx.x) * 4;  // over BR
    int r = idx & (R_SZ - 1);

    float4 cur = *(const float4*)(g_cur + (size_t)t * BR + idx);
    float4 s = make_float4(0.f, 0.f, 0.f, 0.f);
#pragma unroll 4
    for (int ks = 0; ks < nsplit; ks++) {
        float4 pv = *(const float4*)(g_part + (size_t)ks * BR + idx);
        s.x += pv.x; s.y += pv.y; s.z += pv.z; s.w += pv.w;
    }
    float4 br  = *(const float4*)(brec + r);
    float4 syn = *(float4*)(g_syn + idx);
    float4 mem = *(float4*)(g_mem + idx);

    float4 synN, memN, spk;
    {
        synN.x = ALPHA * syn.x + cur.x + s.x + br.x;
        float reset = (mem.x > 1.0f) ? 1.0f : 0.0f;
        memN.x = BETA * mem.x + synN.x - reset;
        spk.x = (memN.x > 1.0f) ? 1.0f : 0.0f;

        synN.y = ALPHA * syn.y + cur.y + s.y + br.y;
        reset = (mem.y > 1.0f) ? 1.0f : 0.0f;
        memN.y = BETA * mem.y + synN.y - reset;
        spk.y = (memN.y > 1.0f) ? 1.0f : 0.0f;

        synN.z = ALPHA * syn.z + cur.z + s.z + br.z;
        reset = (mem.z > 1.0f) ? 1.0f : 0.0f;
        memN.z = BETA * mem.z + synN.z - reset;
        spk.z = (memN.z > 1.0f) ? 1.0f : 0.0f;

        synN.w = ALPHA * syn.w + cur.w + s.w + br.w;
        reset = (mem.w > 1.0f) ? 1.0f : 0.0f;
        memN.w = BETA * mem.w + synN.w - reset;
        spk.w = (memN.w > 1.0f) ? 1.0f : 0.0f;
    }
    *(float4*)(g_syn + idx) = synN;
    *(float4*)(g_mem + idx) = memN;
    *(float4*)(g_spk + (size_t)t * BR + idx) = spk;
    if (spk_out) *(float4*)(spk_out + (size_t)t * BR + idx) = spk;
}

// ---------------- readout mean over each partition ----------------
__global__ void k_ro_reduce() {
    int e = (blockIdx.x * 256 + threadIdx.x) * 4;   // over B*3R = 393216
    int b = e / (3 * R_SZ);
    int c = e % (3 * R_SZ);
    int p = c >> 10;
    int r = c & (R_SZ - 1);
    const float* base = g_spk + ((size_t)(p * PS) * B_SZ + b) * R_SZ + r;
    float4 s = make_float4(0.f, 0.f, 0.f, 0.f);
#pragma unroll 8
    for (int st = 0; st < PS; st++) {
        float4 v = *(const float4*)(base + (size_t)st * BR);
        s.x += v.x; s.y += v.y; s.z += v.z; s.w += v.w;
    }
    float inv = 1.0f / (float)PS;
    s.x *= inv; s.y *= inv; s.z *= inv; s.w *= inv;
    *(float4*)(g_ro + e) = s;
}

// ---------------- final readout GEMM + softmax ----------------
__global__ void k_readout(float* __restrict__ out,
                          const float* __restrict__ Wro,
                          const float* __restrict__ bro) {
    int b = blockIdx.x;
    __shared__ float ro_s[3 * R_SZ];
    __shared__ float logit[112];
    __shared__ float red_sum;
    int tid = threadIdx.x;  // 128 threads

    for (int i = tid * 4; i < 3 * R_SZ; i += 512)
        *(float4*)&ro_s[i] = *(const float4*)(g_ro + (size_t)b * 3 * R_SZ + i);
    __syncthreads();

    int warp = tid >> 5, lane = tid & 31;
    for (int o = warp; o < OUT_SZ; o += 4) {
        const float* w = Wro + (size_t)o * (3 * R_SZ);
        float p0 = 0.f;
        for (int k = lane; k < 3 * R_SZ; k += 32) p0 += ro_s[k] * __ldg(w + k);
#pragma unroll
        for (int off = 16; off; off >>= 1) p0 += __shfl_xor_sync(0xffffffffu, p0, off);
        if (lane == 0) logit[o] = p0 + __ldg(bro + o);
    }
    __syncthreads();
    if (warp == 0) {
        float m = -1e30f;
        for (int i = lane; i < OUT_SZ; i += 32) m = fmaxf(m, logit[i]);
#pragma unroll
        for (int off = 16; off; off >>= 1) m = fmaxf(m, __shfl_xor_sync(0xffffffffu, m, off));
        float sm = 0.f;
        for (int i = lane; i < OUT_SZ; i += 32) {
            float e = expf(logit[i] - m);
            logit[i] = e;
            sm += e;
        }
#pragma unroll
        for (int off = 16; off; off >>= 1) sm += __shfl_xor_sync(0xffffffffu, sm, off);
        if (lane == 0) red_sum = sm;
    }
    __syncthreads();
    float inv = 1.0f / red_sum;
    for (int i = tid; i < OUT_SZ; i += 128)
        out[(size_t)b * OUT_SZ + i] = logit[i] * inv;
}

// ---------------- launcher ----------------
extern "C" void kernel_launch(void* const* d_in, const int* in_sizes, int n_in,
                              void* d_out, int out_size) {
    const float* x     = (const float*)d_in[0];
    const float* W_in  = (const float*)d_in[1];
    const float* b_in  = (const float*)d_in[2];
    const float* W_lin = (const float*)d_in[3];
    const float* W_rec = (const float*)d_in[4];
    const float* b_rec = (const float*)d_in[5];
    const float* W_ro  = (const float*)d_in[6];
    const float* b_ro  = (const float*)d_in[7];

    float* out_main = (float*)d_out;
    float* spk_out  = nullptr;
    if (out_size >= OUT_ELEMS + SPK_ELEMS) {
        spk_out = (float*)d_out + OUT_ELEMS;
    } else if (out_size == SPK_ELEMS) {
        spk_out = (float*)d_out;
        out_main = nullptr;
    }

    k_init<<<128, 256>>>();
    k_input_gemm<<<dim3(R_SZ / 128, (T_STEPS * B_SZ) / 128), 256>>>(x, W_in, b_in);

    for (int t = 0; t < T_STEPS; t++) {
        int nsplit = (t == 0) ? 0 : ((t > PS) ? 8 : 4);
        if (nsplit)
            k_step_gemm<<<dim3(16, nsplit), 256>>>(t, W_rec, W_lin);
        k_update<<<128, 256>>>(t, nsplit, spk_out, b_rec);
    }

    k_ro_reduce<<<384, 256>>>();
    if (out_main) k_readout<<<B_SZ, 128>>>(out_main, W_ro, b_ro);
}

// round 12
// speedup vs baseline: 1.8811x; 1.0133x over previous
#include <cuda_runtime.h>

// ---------------- problem constants ----------------
#define T_STEPS 192
#define B_SZ    128
#define IN_SZ   512
#define R_SZ    1024
#define OUT_SZ  100
#define PS      64
#define BR      (B_SZ * R_SZ)          // 131072
#define SPK_ELEMS (T_STEPS * BR)       // 25165824
#define OUT_ELEMS (B_SZ * OUT_SZ)      // 12800
#define ALPHA 0.9f
#define BETA  0.9f

#define GK 256                 // K per split chunk (association FROZEN: matches R1/R6)
#define NSPLIT_MAX 8
#define ASTRIDE 68             // As[kk][m] row stride (64 m + pad)
#define WSTRIDE 68             // Ws[kk][n] row stride (64 n + pad)

// ---------------- device scratch ----------------
__device__ float g_cur[T_STEPS * BR];    // input projection (+b_in)
__device__ float g_spk[T_STEPS * BR];    // spike history fp32
__device__ float g_syn[BR];
__device__ float g_mem[BR];
__device__ float g_part[NSPLIT_MAX * BR];// split-K partials
__device__ float g_ro[B_SZ * 3 * R_SZ];  // readout input

typedef unsigned long long ull;

__device__ __forceinline__ ull pack2(float lo, float hi) {
    ull r; asm("mov.b64 %0, {%1,%2};" : "=l"(r) : "f"(lo), "f"(hi)); return r;
}
__device__ __forceinline__ void fma2(ull &d, ull a, ull b) {
    asm("fma.rn.f32x2 %0, %1, %2, %0;" : "+l"(d) : "l"(a), "l"(b));
}
__device__ __forceinline__ float2 unpack2(ull v) {
    float2 r; asm("mov.b64 {%0,%1}, %2;" : "=f"(r.x), "=f"(r.y) : "l"(v)); return r;
}

// ---------------- init: zero syn/mem ----------------
__global__ void k_init() {
    int i = blockIdx.x * blockDim.x + threadIdx.x;
    float4 z = make_float4(0.f, 0.f, 0.f, 0.f);
    *(float4*)(g_syn + i * 4) = z;
    *(float4*)(g_mem + i * 4) = z;
}

// ---------------- input projection GEMM (R1, known-correct) ----------------
__global__ void k_input_gemm(const float* __restrict__ X,
                             const float* __restrict__ Win,
                             const float* __restrict__ bin) {
    __shared__ float As[16][128];
    __shared__ float Bs[16][128];
    int tid = threadIdx.x;
    int n0 = blockIdx.x * 128;
    int m0 = blockIdx.y * 128;
    int p  = m0 >> 13;
    const float* A = X + (size_t)m0 * IN_SZ;
    const float* W = Win + (size_t)p * R_SZ * IN_SZ + (size_t)n0 * IN_SZ;

    int lr = tid >> 2;
    int lk = (tid & 3) * 4;
    int tx = tid & 15, ty = tid >> 4;

    ull acc[8][4];
#pragma unroll
    for (int i = 0; i < 8; i++)
#pragma unroll
        for (int j = 0; j < 4; j++) acc[i][j] = 0ULL;

    for (int k0 = 0; k0 < IN_SZ; k0 += 16) {
        float4 a0 = *(const float4*)(A + (size_t)lr * IN_SZ + k0 + lk);
        float4 a1 = *(const float4*)(A + (size_t)(lr + 64) * IN_SZ + k0 + lk);
        float4 b0 = *(const float4*)(W + (size_t)lr * IN_SZ + k0 + lk);
        float4 b1 = *(const float4*)(W + (size_t)(lr + 64) * IN_SZ + k0 + lk);
        __syncthreads();
        As[lk + 0][lr] = a0.x; As[lk + 1][lr] = a0.y; As[lk + 2][lr] = a0.z; As[lk + 3][lr] = a0.w;
        As[lk + 0][lr + 64] = a1.x; As[lk + 1][lr + 64] = a1.y; As[lk + 2][lr + 64] = a1.z; As[lk + 3][lr + 64] = a1.w;
        Bs[lk + 0][lr] = b0.x; Bs[lk + 1][lr] = b0.y; Bs[lk + 2][lr] = b0.z; Bs[lk + 3][lr] = b0.w;
        Bs[lk + 0][lr + 64] = b1.x; Bs[lk + 1][lr + 64] = b1.y; Bs[lk + 2][lr + 64] = b1.z; Bs[lk + 3][lr + 64] = b1.w;
        __syncthreads();
#pragma unroll
        for (int kk = 0; kk < 16; kk++) {
            float4 af0 = *(float4*)&As[kk][ty * 8];
            float4 af1 = *(float4*)&As[kk][ty * 8 + 4];
            float4 bf0 = *(float4*)&Bs[kk][tx * 8];
            float4 bf1 = *(float4*)&Bs[kk][tx * 8 + 4];
            ull b2[4] = { pack2(bf0.x, bf0.y), pack2(bf0.z, bf0.w),
                          pack2(bf1.x, bf1.y), pack2(bf1.z, bf1.w) };
            float am[8] = { af0.x, af0.y, af0.z, af0.w, af1.x, af1.y, af1.z, af1.w };
#pragma unroll
            for (int i = 0; i < 8; i++) {
                ull a2 = pack2(am[i], am[i]);
#pragma unroll
                for (int j = 0; j < 4; j++) fma2(acc[i][j], a2, b2[j]);
            }
        }
    }
    float* C = g_cur + (size_t)m0 * R_SZ + n0;
#pragma unroll
    for (int i = 0; i < 8; i++) {
        int m = ty * 8 + i;
#pragma unroll
        for (int j = 0; j < 4; j++) {
            float2 v = unpack2(acc[i][j]);
            int n = tx * 8 + j * 2;
            C[(size_t)m * R_SZ + n]     = v.x + __ldg(bin + n0 + n);
            C[(size_t)m * R_SZ + n + 1] = v.y + __ldg(bin + n0 + n + 1);
        }
    }
}

// ---------------- per-step recurrent GEMM v6 (R6 engine, M split) ----------------
// grid (16 nt, 2 mt, nsplit), 128 threads. CTA: 64m x 64n, K = 256 chunk.
// ks<4: spk(t-1)@Wrec^T chunk ks*256 ; ks>=4: spk(t-PS)@Wlin^T chunk (ks-4)*256.
// smem: As[32][ASTRIDE] (k-major), Ws[32][WSTRIDE] (k-major), single-buffered,
// register-prefetched in 8 stages of 32 k — EXACTLY R6's staging pattern.
// Thread (tx=tid&15, ty=tid>>4, ty 0..7): m = ty*8+{0..7}, n = tx*4+{0..3}.
// Per-output accumulation: one fma per k, k ascending 0..255 == R6 arithmetic.
__global__ void __launch_bounds__(128)
k_step_gemm(int t,
            const float* __restrict__ Wrec,
            const float* __restrict__ Wlin) {
    const int ks = blockIdx.z;
    const int nt = blockIdx.x;
    const int mt = blockIdx.y;
    const int tid = threadIdx.x;

    const int tsrc = (ks < 4) ? (t - 1) : (t - PS);
    const int kofs = (ks & 3) * GK;
    const float* Asrc = g_spk + (size_t)tsrc * BR + (size_t)(mt * 64) * R_SZ + kofs;
    const float* Wsrc = ((ks < 4) ? Wrec : Wlin) + (size_t)(nt * 64) * R_SZ + kofs;

    __shared__ float As[32 * ASTRIDE];
    __shared__ float Ws[32 * WSTRIDE];

    // load mapping (both operands): row = tid>>1 (0..63), 2 threads cover 32 k
    // as 4 float4 each: thread covers k floats (tid&1)*16 .. +15
    const int lrw = tid >> 1;
    const int lkq = (tid & 1) * 4;

    const int tx = tid & 15, ty = tid >> 4;

    ull acc[8][2];
#pragma unroll
    for (int i = 0; i < 8; i++) { acc[i][0] = 0ULL; acc[i][1] = 0ULL; }

    // prefetch stage 0
    float4 ar[4], wr[4];
#pragma unroll
    for (int j = 0; j < 4; j++) {
        ar[j] = *(const float4*)(Asrc + (size_t)lrw * R_SZ + (lkq + j) * 4);
        wr[j] = *(const float4*)(Wsrc + (size_t)lrw * R_SZ + (lkq + j) * 4);
    }

#pragma unroll
    for (int s = 0; s < 8; s++) {
        __syncthreads();
        // store prefetched regs to smem (k-major, transposed)
#pragma unroll
        for (int j = 0; j < 4; j++) {
            int kk = (lkq + j) * 4;
            As[(kk + 0) * ASTRIDE + lrw] = ar[j].x;
            As[(kk + 1) * ASTRIDE + lrw] = ar[j].y;
            As[(kk + 2) * ASTRIDE + lrw] = ar[j].z;
            As[(kk + 3) * ASTRIDE + lrw] = ar[j].w;
            Ws[(kk + 0) * WSTRIDE + lrw] = wr[j].x;
            Ws[(kk + 1) * WSTRIDE + lrw] = wr[j].y;
            Ws[(kk + 2) * WSTRIDE + lrw] = wr[j].z;
            Ws[(kk + 3) * WSTRIDE + lrw] = wr[j].w;
        }
        __syncthreads();
        // prefetch next stage
        if (s + 1 < 8) {
            const float* An = Asrc + (size_t)lrw * R_SZ + (s + 1) * 32;
            const float* Wn = Wsrc + (size_t)lrw * R_SZ + (s + 1) * 32;
#pragma unroll
            for (int j = 0; j < 4; j++) {
                ar[j] = *(const float4*)(An + (lkq + j) * 4);
                wr[j] = *(const float4*)(Wn + (lkq + j) * 4);
            }
        }
        // compute stage s: kk 0..31 (global k ascending)
#pragma unroll 8
        for (int kk = 0; kk < 32; kk++) {
            float4 a0 = *(float4*)&As[kk * ASTRIDE + ty * 8];
            float4 a1 = *(float4*)&As[kk * ASTRIDE + ty * 8 + 4];
            float4 w  = *(float4*)&Ws[kk * WSTRIDE + tx * 4];
            ull wb0 = pack2(w.x, w.y);
            ull wb1 = pack2(w.z, w.w);
            float am8[8] = { a0.x, a0.y, a0.z, a0.w, a1.x, a1.y, a1.z, a1.w };
#pragma unroll
            for (int i = 0; i < 8; i++) {
                ull a2 = pack2(am8[i], am8[i]);
                fma2(acc[i][0], a2, wb0);
                fma2(acc[i][1], a2, wb1);
            }
        }
    }

    // epilogue: partial tile
    float* C = g_part + (size_t)ks * BR + (size_t)(mt * 64) * R_SZ + nt * 64;
#pragma unroll
    for (int i = 0; i < 8; i++) {
        int m = ty * 8 + i;
        float2 v01 = unpack2(acc[i][0]);
        float2 v23 = unpack2(acc[i][1]);
        float4 v = make_float4(v01.x, v01.y, v23.x, v23.y);
        *(float4*)(C + (size_t)m * R_SZ + tx * 4) = v;
    }
}

// ---------------- per-step state update (R6, nsplit-aware) ----------------
__global__ void k_update(int t, int nsplit, float* __restrict__ spk_out,
                         const float* __restrict__ brec) {
    int idx = (blockIdx.x * 256 + threadIdx.x) * 4;  // over BR
    int r = idx & (R_SZ - 1);

    float4 cur = *(const float4*)(g_cur + (size_t)t * BR + idx);
    float4 s = make_float4(0.f, 0.f, 0.f, 0.f);
#pragma unroll 4
    for (int ks = 0; ks < nsplit; ks++) {
        float4 pv = *(const float4*)(g_part + (size_t)ks * BR + idx);
        s.x += pv.x; s.y += pv.y; s.z += pv.z; s.w += pv.w;
    }
    float4 br  = *(const float4*)(brec + r);
    float4 syn = *(float4*)(g_syn + idx);
    float4 mem = *(float4*)(g_mem + idx);

    float4 synN, memN, spk;
    {
        synN.x = ALPHA * syn.x + cur.x + s.x + br.x;
        float reset = (mem.x > 1.0f) ? 1.0f : 0.0f;
        memN.x = BETA * mem.x + synN.x - reset;
        spk.x = (memN.x > 1.0f) ? 1.0f : 0.0f;

        synN.y = ALPHA * syn.y + cur.y + s.y + br.y;
        reset = (mem.y > 1.0f) ? 1.0f : 0.0f;
        memN.y = BETA * mem.y + synN.y - reset;
        spk.y = (memN.y > 1.0f) ? 1.0f : 0.0f;

        synN.z = ALPHA * syn.z + cur.z + s.z + br.z;
        reset = (mem.z > 1.0f) ? 1.0f : 0.0f;
        memN.z = BETA * mem.z + synN.z - reset;
        spk.z = (memN.z > 1.0f) ? 1.0f : 0.0f;

        synN.w = ALPHA * syn.w + cur.w + s.w + br.w;
        reset = (mem.w > 1.0f) ? 1.0f : 0.0f;
        memN.w = BETA * mem.w + synN.w - reset;
        spk.w = (memN.w > 1.0f) ? 1.0f : 0.0f;
    }
    *(float4*)(g_syn + idx) = synN;
    *(float4*)(g_mem + idx) = memN;
    *(float4*)(g_spk + (size_t)t * BR + idx) = spk;
    if (spk_out) *(float4*)(spk_out + (size_t)t * BR + idx) = spk;
}

// ---------------- readout mean over each partition ----------------
__global__ void k_ro_reduce() {
    int e = (blockIdx.x * 256 + threadIdx.x) * 4;   // over B*3R = 393216
    int b = e / (3 * R_SZ);
    int c = e % (3 * R_SZ);
    int p = c >> 10;
    int r = c & (R_SZ - 1);
    const float* base = g_spk + ((size_t)(p * PS) * B_SZ + b) * R_SZ + r;
    float4 s = make_float4(0.f, 0.f, 0.f, 0.f);
#pragma unroll 8
    for (int st = 0; st < PS; st++) {
        float4 v = *(const float4*)(base + (size_t)st * BR);
        s.x += v.x; s.y += v.y; s.z += v.z; s.w += v.w;
    }
    float inv = 1.0f / (float)PS;
    s.x *= inv; s.y *= inv; s.z *= inv; s.w *= inv;
    *(float4*)(g_ro + e) = s;
}

// ---------------- final readout GEMM + softmax ----------------
__global__ void k_readout(float* __restrict__ out,
                          const float* __restrict__ Wro,
                          const float* __restrict__ bro) {
    int b = blockIdx.x;
    __shared__ float ro_s[3 * R_SZ];
    __shared__ float logit[112];
    __shared__ float red_sum;
    int tid = threadIdx.x;  // 128 threads

    for (int i = tid * 4; i < 3 * R_SZ; i += 512)
        *(float4*)&ro_s[i] = *(const float4*)(g_ro + (size_t)b * 3 * R_SZ + i);
    __syncthreads();

    int warp = tid >> 5, lane = tid & 31;
    for (int o = warp; o < OUT_SZ; o += 4) {
        const float* w = Wro + (size_t)o * (3 * R_SZ);
        float p0 = 0.f;
        for (int k = lane; k < 3 * R_SZ; k += 32) p0 += ro_s[k] * __ldg(w + k);
#pragma unroll
        for (int off = 16; off; off >>= 1) p0 += __shfl_xor_sync(0xffffffffu, p0, off);
        if (lane == 0) logit[o] = p0 + __ldg(bro + o);
    }
    __syncthreads();
    if (warp == 0) {
        float m = -1e30f;
        for (int i = lane; i < OUT_SZ; i += 32) m = fmaxf(m, logit[i]);
#pragma unroll
        for (int off = 16; off; off >>= 1) m = fmaxf(m, __shfl_xor_sync(0xffffffffu, m, off));
        float sm = 0.f;
        for (int i = lane; i < OUT_SZ; i += 32) {
            float e = expf(logit[i] - m);
            logit[i] = e;
            sm += e;
        }
#pragma unroll
        for (int off = 16; off; off >>= 1) sm += __shfl_xor_sync(0xffffffffu, sm, off);
        if (lane == 0) red_sum = sm;
    }
    __syncthreads();
    float inv = 1.0f / red_sum;
    for (int i = tid; i < OUT_SZ; i += 128)
        out[(size_t)b * OUT_SZ + i] = logit[i] * inv;
}

// ---------------- launcher ----------------
extern "C" void kernel_launch(void* const* d_in, const int* in_sizes, int n_in,
                              void* d_out, int out_size) {
    const float* x     = (const float*)d_in[0];
    const float* W_in  = (const float*)d_in[1];
    const float* b_in  = (const float*)d_in[2];
    const float* W_lin = (const float*)d_in[3];
    const float* W_rec = (const float*)d_in[4];
    const float* b_rec = (const float*)d_in[5];
    const float* W_ro  = (const float*)d_in[6];
    const float* b_ro  = (const float*)d_in[7];

    float* out_main = (float*)d_out;
    float* spk_out  = nullptr;
    if (out_size >= OUT_ELEMS + SPK_ELEMS) {
        spk_out = (float*)d_out + OUT_ELEMS;
    } else if (out_size == SPK_ELEMS) {
        spk_out = (float*)d_out;
        out_main = nullptr;
    }

    k_init<<<128, 256>>>();
    k_input_gemm<<<dim3(R_SZ / 128, (T_STEPS * B_SZ) / 128), 256>>>(x, W_in, b_in);

    for (int t = 0; t < T_STEPS; t++) {
        int nsplit = (t == 0) ? 0 : ((t > PS) ? 8 : 4);
        if (nsplit)
            k_step_gemm<<<dim3(16, 2, nsplit), 128>>>(t, W_rec, W_lin);
        k_update<<<128, 256>>>(t, nsplit, spk_out, b_rec);
    }

    k_ro_reduce<<<384, 256>>>();
    if (out_main) k_readout<<<B_SZ, 128>>>(out_main, W_ro, b_ro);
}

// round 13
// speedup vs baseline: 1.9669x; 1.0456x over previous
#include <cuda_runtime.h>

// ---------------- problem constants ----------------
#define T_STEPS 192
#define B_SZ    128
#define IN_SZ   512
#define R_SZ    1024
#define OUT_SZ  100
#define PS      64
#define BR      (B_SZ * R_SZ)          // 131072
#define SPK_ELEMS (T_STEPS * BR)       // 25165824
#define OUT_ELEMS (B_SZ * OUT_SZ)      // 12800
#define ALPHA 0.9f
#define BETA  0.9f

#define GK 256                 // K per split chunk (association FROZEN)
#define NSPLIT_MAX 8
#define TSTRIDE 68             // smem row stride (64 + pad)

// ---------------- device scratch ----------------
__device__ float g_cur[T_STEPS * BR];    // input projection (+b_in)
__device__ float g_spk[T_STEPS * BR];    // spike history fp32
__device__ float g_syn[BR];
__device__ float g_mem[BR];
__device__ float g_part[NSPLIT_MAX * BR];// split-K partials
__device__ float g_ro[B_SZ * 3 * R_SZ];  // readout input

typedef unsigned long long ull;

__device__ __forceinline__ ull pack2(float lo, float hi) {
    ull r; asm("mov.b64 %0, {%1,%2};" : "=l"(r) : "f"(lo), "f"(hi)); return r;
}
__device__ __forceinline__ void fma2(ull &d, ull a, ull b) {
    asm("fma.rn.f32x2 %0, %1, %2, %0;" : "+l"(d) : "l"(a), "l"(b));
}
__device__ __forceinline__ float2 unpack2(ull v) {
    float2 r; asm("mov.b64 {%0,%1}, %2;" : "=f"(r.x), "=f"(r.y) : "l"(v)); return r;
}

// ---------------- init: zero syn/mem ----------------
__global__ void k_init() {
    int i = blockIdx.x * blockDim.x + threadIdx.x;
    float4 z = make_float4(0.f, 0.f, 0.f, 0.f);
    *(float4*)(g_syn + i * 4) = z;
    *(float4*)(g_mem + i * 4) = z;
}

// ---------------- input projection GEMM (R1, known-correct) ----------------
__global__ void k_input_gemm(const float* __restrict__ X,
                             const float* __restrict__ Win,
                             const float* __restrict__ bin) {
    __shared__ float As[16][128];
    __shared__ float Bs[16][128];
    int tid = threadIdx.x;
    int n0 = blockIdx.x * 128;
    int m0 = blockIdx.y * 128;
    int p  = m0 >> 13;
    const float* A = X + (size_t)m0 * IN_SZ;
    const float* W = Win + (size_t)p * R_SZ * IN_SZ + (size_t)n0 * IN_SZ;

    int lr = tid >> 2;
    int lk = (tid & 3) * 4;
    int tx = tid & 15, ty = tid >> 4;

    ull acc[8][4];
#pragma unroll
    for (int i = 0; i < 8; i++)
#pragma unroll
        for (int j = 0; j < 4; j++) acc[i][j] = 0ULL;

    for (int k0 = 0; k0 < IN_SZ; k0 += 16) {
        float4 a0 = *(const float4*)(A + (size_t)lr * IN_SZ + k0 + lk);
        float4 a1 = *(const float4*)(A + (size_t)(lr + 64) * IN_SZ + k0 + lk);
        float4 b0 = *(const float4*)(W + (size_t)lr * IN_SZ + k0 + lk);
        float4 b1 = *(const float4*)(W + (size_t)(lr + 64) * IN_SZ + k0 + lk);
        __syncthreads();
        As[lk + 0][lr] = a0.x; As[lk + 1][lr] = a0.y; As[lk + 2][lr] = a0.z; As[lk + 3][lr] = a0.w;
        As[lk + 0][lr + 64] = a1.x; As[lk + 1][lr + 64] = a1.y; As[lk + 2][lr + 64] = a1.z; As[lk + 3][lr + 64] = a1.w;
        Bs[lk + 0][lr] = b0.x; Bs[lk + 1][lr] = b0.y; Bs[lk + 2][lr] = b0.z; Bs[lk + 3][lr] = b0.w;
        Bs[lk + 0][lr + 64] = b1.x; Bs[lk + 1][lr + 64] = b1.y; Bs[lk + 2][lr + 64] = b1.z; Bs[lk + 3][lr + 64] = b1.w;
        __syncthreads();
#pragma unroll
        for (int kk = 0; kk < 16; kk++) {
            float4 af0 = *(float4*)&As[kk][ty * 8];
            float4 af1 = *(float4*)&As[kk][ty * 8 + 4];
            float4 bf0 = *(float4*)&Bs[kk][tx * 8];
            float4 bf1 = *(float4*)&Bs[kk][tx * 8 + 4];
            ull b2[4] = { pack2(bf0.x, bf0.y), pack2(bf0.z, bf0.w),
                          pack2(bf1.x, bf1.y), pack2(bf1.z, bf1.w) };
            float am[8] = { af0.x, af0.y, af0.z, af0.w, af1.x, af1.y, af1.z, af1.w };
#pragma unroll
            for (int i = 0; i < 8; i++) {
                ull a2 = pack2(am[i], am[i]);
#pragma unroll
                for (int j = 0; j < 4; j++) fma2(acc[i][j], a2, b2[j]);
            }
        }
    }
    float* C = g_cur + (size_t)m0 * R_SZ + n0;
#pragma unroll
    for (int i = 0; i < 8; i++) {
        int m = ty * 8 + i;
#pragma unroll
        for (int j = 0; j < 4; j++) {
            float2 v = unpack2(acc[i][j]);
            int n = tx * 8 + j * 2;
            C[(size_t)m * R_SZ + n]     = v.x + __ldg(bin + n0 + n);
            C[(size_t)m * R_SZ + n + 1] = v.y + __ldg(bin + n0 + n + 1);
        }
    }
}

// ---------------- per-step recurrent GEMM v7 (256 thr, double-buffered) ----------------
// grid (16 nt, 2 mt, nsplit), 256 threads. CTA: 64m x 64n, K = 256 chunk.
// ks<4: spk(t-1)@Wrec^T chunk ks*256 ; ks>=4: spk(t-PS)@Wlin^T chunk (ks-4)*256.
// smem: As/Ws [2 buf][32 kk][TSTRIDE] k-major; register-prefetched LDG->STS,
// double-buffered, ONE __syncthreads per stage.
// Thread (tx=tid&15, ty=tid>>4, ty 0..15): m = ty*4+{0..3}, n = tx*4+{0..3}.
// Per-output accumulation: one fma per k, k ascending 0..255 == R6/R12 arithmetic.
__global__ void __launch_bounds__(256)
k_step_gemm(int t,
            const float* __restrict__ Wrec,
            const float* __restrict__ Wlin) {
    const int ks = blockIdx.z;
    const int nt = blockIdx.x;
    const int mt = blockIdx.y;
    const int tid = threadIdx.x;

    const int tsrc = (ks < 4) ? (t - 1) : (t - PS);
    const int kofs = (ks & 3) * GK;
    const float* Asrc = g_spk + (size_t)tsrc * BR + (size_t)(mt * 64) * R_SZ + kofs;
    const float* Wsrc = ((ks < 4) ? Wrec : Wlin) + (size_t)(nt * 64) * R_SZ + kofs;

    __shared__ float As[2][32 * TSTRIDE];
    __shared__ float Ws[2][32 * TSTRIDE];

    // load mapping: row = tid>>2 (0..63), 4 threads cover 32 k as 2 float4 each:
    // thread covers float4 indices (tid&3)*2 + {0,1}
    const int lrw = tid >> 2;
    const int lkq = (tid & 3) * 2;

    const int tx = tid & 15, ty = tid >> 4;

    ull acc[4][2];
#pragma unroll
    for (int i = 0; i < 4; i++) { acc[i][0] = 0ULL; acc[i][1] = 0ULL; }

    // prefetch + store stage 0
    float4 ar[2], wr[2];
#pragma unroll
    for (int j = 0; j < 2; j++) {
        ar[j] = *(const float4*)(Asrc + (size_t)lrw * R_SZ + (lkq + j) * 4);
        wr[j] = *(const float4*)(Wsrc + (size_t)lrw * R_SZ + (lkq + j) * 4);
    }
#pragma unroll
    for (int j = 0; j < 2; j++) {
        int kk = (lkq + j) * 4;
        As[0][(kk + 0) * TSTRIDE + lrw] = ar[j].x;
        As[0][(kk + 1) * TSTRIDE + lrw] = ar[j].y;
        As[0][(kk + 2) * TSTRIDE + lrw] = ar[j].z;
        As[0][(kk + 3) * TSTRIDE + lrw] = ar[j].w;
        Ws[0][(kk + 0) * TSTRIDE + lrw] = wr[j].x;
        Ws[0][(kk + 1) * TSTRIDE + lrw] = wr[j].y;
        Ws[0][(kk + 2) * TSTRIDE + lrw] = wr[j].z;
        Ws[0][(kk + 3) * TSTRIDE + lrw] = wr[j].w;
    }
    __syncthreads();

#pragma unroll
    for (int s = 0; s < 8; s++) {
        // prefetch next stage from gmem
        if (s + 1 < 8) {
            const float* An = Asrc + (size_t)lrw * R_SZ + (s + 1) * 32;
            const float* Wn = Wsrc + (size_t)lrw * R_SZ + (s + 1) * 32;
#pragma unroll
            for (int j = 0; j < 2; j++) {
                ar[j] = *(const float4*)(An + (lkq + j) * 4);
                wr[j] = *(const float4*)(Wn + (lkq + j) * 4);
            }
        }
        // compute current buffer
        const float* a_ = As[s & 1];
        const float* w_ = Ws[s & 1];
#pragma unroll 8
        for (int kk = 0; kk < 32; kk++) {
            float4 a = *(const float4*)(a_ + kk * TSTRIDE + ty * 4);
            float4 w = *(const float4*)(w_ + kk * TSTRIDE + tx * 4);
            ull wb0 = pack2(w.x, w.y);
            ull wb1 = pack2(w.z, w.w);
            float am4[4] = { a.x, a.y, a.z, a.w };
#pragma unroll
            for (int i = 0; i < 4; i++) {
                ull a2 = pack2(am4[i], am4[i]);
                fma2(acc[i][0], a2, wb0);
                fma2(acc[i][1], a2, wb1);
            }
        }
        // store next stage into the other buffer (its readers finished at stage s-1)
        if (s + 1 < 8) {
            float* ad = As[(s + 1) & 1];
            float* wd = Ws[(s + 1) & 1];
#pragma unroll
            for (int j = 0; j < 2; j++) {
                int kk = (lkq + j) * 4;
                ad[(kk + 0) * TSTRIDE + lrw] = ar[j].x;
                ad[(kk + 1) * TSTRIDE + lrw] = ar[j].y;
                ad[(kk + 2) * TSTRIDE + lrw] = ar[j].z;
                ad[(kk + 3) * TSTRIDE + lrw] = ar[j].w;
                wd[(kk + 0) * TSTRIDE + lrw] = wr[j].x;
                wd[(kk + 1) * TSTRIDE + lrw] = wr[j].y;
                wd[(kk + 2) * TSTRIDE + lrw] = wr[j].z;
                wd[(kk + 3) * TSTRIDE + lrw] = wr[j].w;
            }
        }
        __syncthreads();
    }

    // epilogue: partial tile
    float* C = g_part + (size_t)ks * BR + (size_t)(mt * 64) * R_SZ + nt * 64;
#pragma unroll
    for (int i = 0; i < 4; i++) {
        int m = ty * 4 + i;
        float2 v01 = unpack2(acc[i][0]);
        float2 v23 = unpack2(acc[i][1]);
        float4 v = make_float4(v01.x, v01.y, v23.x, v23.y);
        *(float4*)(C + (size_t)m * R_SZ + tx * 4) = v;
    }
}

// ---------------- per-step state update (float2, nsplit-aware) ----------------
__global__ void k_update(int t, int nsplit, float* __restrict__ spk_out,
                         const float* __restrict__ brec) {
    int idx = (blockIdx.x * 256 + threadIdx.x) * 2;  // over BR, grid 256
    int r = idx & (R_SZ - 1);

    float2 cur = *(const float2*)(g_cur + (size_t)t * BR + idx);
    float2 s = make_float2(0.f, 0.f);
    if (nsplit == 8) {
#pragma unroll
        for (int ks = 0; ks < 8; ks++) {
            float2 pv = *(const float2*)(g_part + (size_t)ks * BR + idx);
            s.x += pv.x; s.y += pv.y;
        }
    } else if (nsplit == 4) {
#pragma unroll
        for (int ks = 0; ks < 4; ks++) {
            float2 pv = *(const float2*)(g_part + (size_t)ks * BR + idx);
            s.x += pv.x; s.y += pv.y;
        }
    }
    float2 br  = *(const float2*)(brec + r);
    float2 syn = *(float2*)(g_syn + idx);
    float2 mem = *(float2*)(g_mem + idx);

    float2 spk;
    syn.x = ALPHA * syn.x + cur.x + s.x + br.x;
    float rs = (mem.x > 1.0f) ? 1.0f : 0.0f;
    mem.x = BETA * mem.x + syn.x - rs;
    spk.x = (mem.x > 1.0f) ? 1.0f : 0.0f;

    syn.y = ALPHA * syn.y + cur.y + s.y + br.y;
    rs = (mem.y > 1.0f) ? 1.0f : 0.0f;
    mem.y = BETA * mem.y + syn.y - rs;
    spk.y = (mem.y > 1.0f) ? 1.0f : 0.0f;

    *(float2*)(g_syn + idx) = syn;
    *(float2*)(g_mem + idx) = mem;
    *(float2*)(g_spk + (size_t)t * BR + idx) = spk;
    if (spk_out) *(float2*)(spk_out + (size_t)t * BR + idx) = spk;
}

// ---------------- readout mean over each partition ----------------
__global__ void k_ro_reduce() {
    int e = (blockIdx.x * 256 + threadIdx.x) * 4;   // over B*3R = 393216
    int b = e / (3 * R_SZ);
    int c = e % (3 * R_SZ);
    int p = c >> 10;
    int r = c & (R_SZ - 1);
    const float* base = g_spk + ((size_t)(p * PS) * B_SZ + b) * R_SZ + r;
    float4 s = make_float4(0.f, 0.f, 0.f, 0.f);
#pragma unroll 8
    for (int st = 0; st < PS; st++) {
        float4 v = *(const float4*)(base + (size_t)st * BR);
        s.x += v.x; s.y += v.y; s.z += v.z; s.w += v.w;
    }
    float inv = 1.0f / (float)PS;
    s.x *= inv; s.y *= inv; s.z *= inv; s.w *= inv;
    *(float4*)(g_ro + e) = s;
}

// ---------------- final readout GEMM + softmax ----------------
__global__ void k_readout(float* __restrict__ out,
                          const float* __restrict__ Wro,
                          const float* __restrict__ bro) {
    int b = blockIdx.x;
    __shared__ float ro_s[3 * R_SZ];
    __shared__ float logit[112];
    __shared__ float red_sum;
    int tid = threadIdx.x;  // 128 threads

    for (int i = tid * 4; i < 3 * R_SZ; i += 512)
        *(float4*)&ro_s[i] = *(const float4*)(g_ro + (size_t)b * 3 * R_SZ + i);
    __syncthreads();

    int warp = tid >> 5, lane = tid & 31;
    for (int o = warp; o < OUT_SZ; o += 4) {
        const float* w = Wro + (size_t)o * (3 * R_SZ);
        float p0 = 0.f;
        for (int k = lane; k < 3 * R_SZ; k += 32) p0 += ro_s[k] * __ldg(w + k);
#pragma unroll
        for (int off = 16; off; off >>= 1) p0 += __shfl_xor_sync(0xffffffffu, p0, off);
        if (lane == 0) logit[o] = p0 + __ldg(bro + o);
    }
    __syncthreads();
    if (warp == 0) {
        float m = -1e30f;
        for (int i = lane; i < OUT_SZ; i += 32) m = fmaxf(m, logit[i]);
#pragma unroll
        for (int off = 16; off; off >>= 1) m = fmaxf(m, __shfl_xor_sync(0xffffffffu, m, off));
        float sm = 0.f;
        for (int i = lane; i < OUT_SZ; i += 32) {
            float e = expf(logit[i] - m);
            logit[i] = e;
            sm += e;
        }
#pragma unroll
        for (int off = 16; off; off >>= 1) sm += __shfl_xor_sync(0xffffffffu, sm, off);
        if (lane == 0) red_sum = sm;
    }
    __syncthreads();
    float inv = 1.0f / red_sum;
    for (int i = tid; i < OUT_SZ; i += 128)
        out[(size_t)b * OUT_SZ + i] = logit[i] * inv;
}

// ---------------- launcher ----------------
extern "C" void kernel_launch(void* const* d_in, const int* in_sizes, int n_in,
                              void* d_out, int out_size) {
    const float* x     = (const float*)d_in[0];
    const float* W_in  = (const float*)d_in[1];
    const float* b_in  = (const float*)d_in[2];
    const float* W_lin = (const float*)d_in[3];
    const float* W_rec = (const float*)d_in[4];
    const float* b_rec = (const float*)d_in[5];
    const float* W_ro  = (const float*)d_in[6];
    const float* b_ro  = (const float*)d_in[7];

    float* out_main = (float*)d_out;
    float* spk_out  = nullptr;
    if (out_size >= OUT_ELEMS + SPK_ELEMS) {
        spk_out = (float*)d_out + OUT_ELEMS;
    } else if (out_size == SPK_ELEMS) {
        spk_out = (float*)d_out;
        out_main = nullptr;
    }

    k_init<<<128, 256>>>();
    k_input_gemm<<<dim3(R_SZ / 128, (T_STEPS * B_SZ) / 128), 256>>>(x, W_in, b_in);

    for (int t = 0; t < T_STEPS; t++) {
        int nsplit = (t == 0) ? 0 : ((t > PS) ? 8 : 4);
        if (nsplit)
            k_step_gemm<<<dim3(16, 2, nsplit), 256>>>(t, W_rec, W_lin);
        k_update<<<256, 256>>>(t, nsplit, spk_out, b_rec);
    }

    k_ro_reduce<<<384, 256>>>();
    if (out_main) k_readout<<<B_SZ, 128>>>(out_main, W_ro, b_ro);
}